// round 1
// baseline (speedup 1.0000x reference)
#include <cuda_runtime.h>
#include <cstdint>

#define B_  64
#define N_  512
#define E_  1024
#define H_  16
#define DH_ 64

// Scratch (allocation-free rule: __device__ globals)
__device__ float g_qkv[(size_t)B_ * N_ * 3 * E_];   // [B*N, 3E], col = s*1024 + h*64 + d
__device__ float g_y[(size_t)B_ * N_ * E_];         // [B*N, E],  col = h*64 + d

// ---------------- packed f32x2 helpers (full-rate FMA on sm_103a) ----------------
__device__ __forceinline__ unsigned long long dup2(float v) {
    unsigned long long r;
    unsigned int u = __float_as_uint(v);
    asm("mov.b64 %0, {%1, %1};" : "=l"(r) : "r"(u));
    return r;
}
__device__ __forceinline__ void fma2(unsigned long long& c, unsigned long long a, unsigned long long b) {
    asm("fma.rn.f32x2 %0, %1, %2, %3;" : "=l"(c) : "l"(a), "l"(b), "l"(c));
}
__device__ __forceinline__ float2 un2(unsigned long long u) {
    float2 f;
    f.x = __uint_as_float((unsigned int)(u & 0xffffffffu));
    f.y = __uint_as_float((unsigned int)(u >> 32));
    return f;
}

// ---------------- GEMM: C[M,N] = A[M,K] @ B[K,N] + bias[N] ----------------
// 128x128 tile, BK=16, 256 threads, 8x8 per thread (f32x2: 4 m-pairs x 8 n)
__global__ __launch_bounds__(256, 2)
void gemm_bias(const float* __restrict__ A, const float* __restrict__ Bm,
               const float* __restrict__ bias, float* __restrict__ C,
               int M, int N, int K)
{
    __shared__ float As[2][16 * 132];   // transposed [k][m], pad 132
    __shared__ float Bs[2][16 * 128];   // [k][n]

    const int tid = threadIdx.x;
    const int tx = tid & 15, ty = tid >> 4;
    const int n0 = blockIdx.x * 128, m0 = blockIdx.y * 128;

    unsigned long long acc[4][8];
#pragma unroll
    for (int i = 0; i < 4; ++i)
#pragma unroll
        for (int j = 0; j < 8; ++j) acc[i][j] = 0ull;

    const int ar = tid >> 2, akq = tid & 3;   // A loader: rows ar, ar+64; k-quad akq
    const int br = tid >> 5, bnq = tid & 31;  // B loader: rows br, br+8;  n-quad bnq

    float4 ra0, ra1, rb0, rb1;

    // prologue: load tile 0
    ra0 = *(const float4*)(A + (size_t)(m0 + ar) * K + akq * 4);
    ra1 = *(const float4*)(A + (size_t)(m0 + ar + 64) * K + akq * 4);
    rb0 = *(const float4*)(Bm + (size_t)(br) * N + n0 + bnq * 4);
    rb1 = *(const float4*)(Bm + (size_t)(br + 8) * N + n0 + bnq * 4);
    {
        float* s = As[0];
        s[(akq*4+0)*132 + ar] = ra0.x; s[(akq*4+1)*132 + ar] = ra0.y;
        s[(akq*4+2)*132 + ar] = ra0.z; s[(akq*4+3)*132 + ar] = ra0.w;
        s[(akq*4+0)*132 + ar+64] = ra1.x; s[(akq*4+1)*132 + ar+64] = ra1.y;
        s[(akq*4+2)*132 + ar+64] = ra1.z; s[(akq*4+3)*132 + ar+64] = ra1.w;
        *(float4*)&Bs[0][br*128 + bnq*4]     = rb0;
        *(float4*)&Bs[0][(br+8)*128 + bnq*4] = rb1;
    }
    __syncthreads();

    const int nk = K / 16;
    int cur = 0;
    for (int kt = 0; kt < nk; ++kt) {
        if (kt + 1 < nk) {
            int k0 = (kt + 1) * 16;
            ra0 = *(const float4*)(A + (size_t)(m0 + ar) * K + k0 + akq * 4);
            ra1 = *(const float4*)(A + (size_t)(m0 + ar + 64) * K + k0 + akq * 4);
            rb0 = *(const float4*)(Bm + (size_t)(k0 + br) * N + n0 + bnq * 4);
            rb1 = *(const float4*)(Bm + (size_t)(k0 + br + 8) * N + n0 + bnq * 4);
        }
        const float* as = As[cur];
        const float* bs = Bs[cur];
#pragma unroll
        for (int kk = 0; kk < 16; ++kk) {
            const unsigned long long* a2 = (const unsigned long long*)(as + kk * 132 + ty * 8);
            unsigned long long av0 = a2[0], av1 = a2[1], av2 = a2[2], av3 = a2[3];
            float4 b0 = *(const float4*)(bs + kk * 128 + tx * 8);
            float4 b1 = *(const float4*)(bs + kk * 128 + tx * 8 + 4);
            unsigned long long bd[8];
            bd[0]=dup2(b0.x); bd[1]=dup2(b0.y); bd[2]=dup2(b0.z); bd[3]=dup2(b0.w);
            bd[4]=dup2(b1.x); bd[5]=dup2(b1.y); bd[6]=dup2(b1.z); bd[7]=dup2(b1.w);
#pragma unroll
            for (int n = 0; n < 8; ++n) {
                fma2(acc[0][n], av0, bd[n]);
                fma2(acc[1][n], av1, bd[n]);
                fma2(acc[2][n], av2, bd[n]);
                fma2(acc[3][n], av3, bd[n]);
            }
        }
        if (kt + 1 < nk) {
            float* s = As[cur ^ 1];
            s[(akq*4+0)*132 + ar] = ra0.x; s[(akq*4+1)*132 + ar] = ra0.y;
            s[(akq*4+2)*132 + ar] = ra0.z; s[(akq*4+3)*132 + ar] = ra0.w;
            s[(akq*4+0)*132 + ar+64] = ra1.x; s[(akq*4+1)*132 + ar+64] = ra1.y;
            s[(akq*4+2)*132 + ar+64] = ra1.z; s[(akq*4+3)*132 + ar+64] = ra1.w;
            *(float4*)&Bs[cur ^ 1][br*128 + bnq*4]     = rb0;
            *(float4*)&Bs[cur ^ 1][(br+8)*128 + bnq*4] = rb1;
            __syncthreads();
            cur ^= 1;
        }
    }

    // epilogue with bias
    const float* bp = bias + n0 + tx * 8;
    float bv[8];
#pragma unroll
    for (int n = 0; n < 8; ++n) bv[n] = bp[n];

#pragma unroll
    for (int mp = 0; mp < 4; ++mp) {
        float lo[8], hi[8];
#pragma unroll
        for (int n = 0; n < 8; ++n) {
            float2 p = un2(acc[mp][n]);
            lo[n] = p.x + bv[n];
            hi[n] = p.y + bv[n];
        }
        int row = m0 + ty * 8 + mp * 2;
        float* c0 = C + (size_t)row * N + n0 + tx * 8;
        float* c1 = C + (size_t)(row + 1) * N + n0 + tx * 8;
        *(float4*)(c0)     = make_float4(lo[0], lo[1], lo[2], lo[3]);
        *(float4*)(c0 + 4) = make_float4(lo[4], lo[5], lo[6], lo[7]);
        *(float4*)(c1)     = make_float4(hi[0], hi[1], hi[2], hi[3]);
        *(float4*)(c1 + 4) = make_float4(hi[4], hi[5], hi[6], hi[7]);
    }
}

// ---------------- Attention: per (b,h,64-query-tile) block ----------------
// smem: S[512][68] score panel, Qt[64][68] (transposed), KV[64][68], reductions
#define SST 68
__global__ __launch_bounds__(256)
void attn_kernel(const float* __restrict__ qkv, const int* __restrict__ adj,
                 float* __restrict__ y)
{
    extern __shared__ float sm[];
    float* S     = sm;                       // 512*68
    float* Qt    = sm + 512 * SST;           // 64*68 (transposed: [d][r])
    float* KV    = Qt + 64 * SST;            // 64*68 (K transposed / V row-major)
    float* red   = KV + 64 * SST;            // 256
    float* rmaxs = red + 256;                // 64
    float* rsums = rmaxs + 64;               // 64

    const int t  = threadIdx.x;
    const int qt = blockIdx.x;               // 0..7
    const int bh = blockIdx.y;               // 0..1023
    const int b  = bh >> 4, h = bh & 15;

    const size_t rowbase = (size_t)b * N_ * (3 * E_);
    const int qcol = h * DH_;
    const int kcol = E_ + h * DH_;
    const int vcol = 2 * E_ + h * DH_;

    // load Q tile (64 rows x 64 d), store transposed Qt[d][r]
#pragma unroll
    for (int i = 0; i < 4; ++i) {
        int fid = t + i * 256;
        int row = fid >> 4, d4 = fid & 15;
        float4 v = *(const float4*)(qkv + rowbase + (size_t)(qt * 64 + row) * (3 * E_) + qcol + d4 * 4);
        Qt[(d4*4+0)*SST + row] = v.x;
        Qt[(d4*4+1)*SST + row] = v.y;
        Qt[(d4*4+2)*SST + row] = v.z;
        Qt[(d4*4+3)*SST + row] = v.w;
    }

    const int tc = t & 15, tr = t >> 4;      // 16x16 thread grid, 4x4 micro-tiles
    const float scale = 0.125f;              // 1/sqrt(64)

    // ---- Phase 1: S^T[c][r] = scale * Q K^T, masked ----
    for (int kt = 0; kt < 8; ++kt) {
        __syncthreads();   // KV free (also covers Qt load at kt=0 w/ next sync)
#pragma unroll
        for (int i = 0; i < 4; ++i) {
            int fid = t + i * 256;
            int row = fid >> 4, d4 = fid & 15;
            float4 v = *(const float4*)(qkv + rowbase + (size_t)(kt * 64 + row) * (3 * E_) + kcol + d4 * 4);
            KV[(d4*4+0)*SST + row] = v.x;
            KV[(d4*4+1)*SST + row] = v.y;
            KV[(d4*4+2)*SST + row] = v.z;
            KV[(d4*4+3)*SST + row] = v.w;
        }
        __syncthreads();

        unsigned long long acc[4][2];
#pragma unroll
        for (int i = 0; i < 4; ++i) { acc[i][0] = 0ull; acc[i][1] = 0ull; }

#pragma unroll 16
        for (int d = 0; d < 64; ++d) {
            float4 kf = *(const float4*)(KV + d * SST + tc * 4);
            const unsigned long long* q2 = (const unsigned long long*)(Qt + d * SST + tr * 4);
            unsigned long long qa = q2[0], qb = q2[1];
            unsigned long long k0 = dup2(kf.x), k1 = dup2(kf.y), k2 = dup2(kf.z), k3 = dup2(kf.w);
            fma2(acc[0][0], k0, qa); fma2(acc[0][1], k0, qb);
            fma2(acc[1][0], k1, qa); fma2(acc[1][1], k1, qb);
            fma2(acc[2][0], k2, qa); fma2(acc[2][1], k2, qb);
            fma2(acc[3][0], k3, qa); fma2(acc[3][1], k3, qb);
        }

        int qg0 = qt * 64 + tr * 4;
#pragma unroll
        for (int ci = 0; ci < 4; ++ci) {
            int kg = kt * 64 + tc * 4 + ci;
            float2 p0 = un2(acc[ci][0]), p1 = un2(acc[ci][1]);
            float vals[4] = { p0.x, p0.y, p1.x, p1.y };
            float o4[4];
#pragma unroll
            for (int ri = 0; ri < 4; ++ri) {
                int qg = qg0 + ri;
                bool m = (adj[qg * N_ + kg] != 0) || (qg == kg);
                o4[ri] = m ? vals[ri] * scale : -1e30f;
            }
            *(float4*)(S + (size_t)kg * SST + tr * 4) =
                make_float4(o4[0], o4[1], o4[2], o4[3]);
        }
    }
    __syncthreads();

    // ---- Phase 2: softmax over each row r (512 entries) ----
    {
        int r = t & 63, seg = t >> 6;
        float mx = -3.0e38f;
#pragma unroll 8
        for (int c = seg * 128; c < seg * 128 + 128; ++c)
            mx = fmaxf(mx, S[c * SST + r]);
        red[seg * 64 + r] = mx;
        __syncthreads();
        if (t < 64)
            rmaxs[t] = fmaxf(fmaxf(red[t], red[64 + t]), fmaxf(red[128 + t], red[192 + t]));
        __syncthreads();
        float rm = rmaxs[r];
        float sum = 0.f;
#pragma unroll 8
        for (int c = seg * 128; c < seg * 128 + 128; ++c) {
            float p = __expf(S[c * SST + r] - rm);
            S[c * SST + r] = p;
            sum += p;
        }
        red[seg * 64 + r] = sum;
        __syncthreads();
        if (t < 64)
            rsums[t] = red[t] + red[64 + t] + red[128 + t] + red[192 + t];
    }

    // ---- Phase 3: O = P V ----
    const int tv = tc;
    unsigned long long oacc[4][2];
#pragma unroll
    for (int i = 0; i < 4; ++i) { oacc[i][0] = 0ull; oacc[i][1] = 0ull; }

    for (int kt = 0; kt < 8; ++kt) {
        __syncthreads();   // also covers rsums write before first V load
#pragma unroll
        for (int i = 0; i < 4; ++i) {
            int fid = t + i * 256;
            int row = fid >> 4, d4 = fid & 15;
            *(float4*)(KV + row * SST + d4 * 4) =
                *(const float4*)(qkv + rowbase + (size_t)(kt * 64 + row) * (3 * E_) + vcol + d4 * 4);
        }
        __syncthreads();

#pragma unroll 16
        for (int j = 0; j < 64; ++j) {
            float4 pf = *(const float4*)(S + (size_t)(kt * 64 + j) * SST + tr * 4);
            const unsigned long long* v2 = (const unsigned long long*)(KV + j * SST + tv * 4);
            unsigned long long va = v2[0], vb = v2[1];
            unsigned long long p0 = dup2(pf.x), p1 = dup2(pf.y), p2 = dup2(pf.z), p3 = dup2(pf.w);
            fma2(oacc[0][0], p0, va); fma2(oacc[0][1], p0, vb);
            fma2(oacc[1][0], p1, va); fma2(oacc[1][1], p1, vb);
            fma2(oacc[2][0], p2, va); fma2(oacc[2][1], p2, vb);
            fma2(oacc[3][0], p3, va); fma2(oacc[3][1], p3, vb);
        }
    }

    // epilogue: normalize, write y[b, n, h*64+v]
#pragma unroll
    for (int ri = 0; ri < 4; ++ri) {
        int r = tr * 4 + ri;
        float inv = 1.0f / rsums[r];
        float2 p0 = un2(oacc[ri][0]), p1 = un2(oacc[ri][1]);
        float4 o = make_float4(p0.x * inv, p0.y * inv, p1.x * inv, p1.y * inv);
        *(float4*)(y + (size_t)(b * N_ + qt * 64 + r) * E_ + h * DH_ + tv * 4) = o;
    }
}

// ---------------- launch ----------------
extern "C" void kernel_launch(void* const* d_in, const int* in_sizes, int n_in,
                              void* d_out, int out_size) {
    const float* x     = (const float*)d_in[0];
    const float* Wqkv  = (const float*)d_in[1];
    const float* bqkv  = (const float*)d_in[2];
    const float* Wproj = (const float*)d_in[3];
    const float* bproj = (const float*)d_in[4];
    const int*   adj   = (const int*)d_in[5];

    float* qkv = nullptr;
    float* yb  = nullptr;
    cudaGetSymbolAddress((void**)&qkv, g_qkv);
    cudaGetSymbolAddress((void**)&yb,  g_y);

    const int ATT_SMEM = (512 * SST + 2 * 64 * SST + 256 + 128) * (int)sizeof(float);
    cudaFuncSetAttribute(attn_kernel, cudaFuncAttributeMaxDynamicSharedMemorySize, ATT_SMEM);

    // 1) QKV projection: [32768,1024] @ [1024,3072] + bqkv
    dim3 g1(3 * E_ / 128, (B_ * N_) / 128);
    gemm_bias<<<g1, 256>>>(x, Wqkv, bqkv, qkv, B_ * N_, 3 * E_, E_);

    // 2) masked attention
    dim3 ga(N_ / 64, B_ * H_);
    attn_kernel<<<ga, 256, ATT_SMEM>>>(qkv, adj, yb);

    // 3) output projection: [32768,1024] @ [1024,1024] + bproj
    dim3 g3(E_ / 128, (B_ * N_) / 128);
    gemm_bias<<<g3, 256>>>(yb, Wproj, bproj, (float*)d_out, B_ * N_, E_, E_);
}

// round 4
// speedup vs baseline: 1.8387x; 1.8387x over previous
#include <cuda_runtime.h>
#include <cstdint>

#define B_  64
#define N_  512
#define E_  1024
#define H_  16
#define DH_ 64

// Scratch (allocation-free rule: __device__ globals)
__device__ float g_qkv[(size_t)B_ * N_ * 3 * E_];   // [B*N, 3E]
__device__ float g_y[(size_t)B_ * N_ * E_];         // [B*N, E]
__device__ float g_xr[(size_t)B_ * N_ * E_];        // tf32-rounded x
__device__ float g_wqkvT[(size_t)3 * E_ * E_];      // [3E, E] = Wqkv^T, tf32-rounded
__device__ float g_wprojT[(size_t)E_ * E_];         // [E, E]  = Wproj^T, tf32-rounded

// ================= helpers =================
__device__ __forceinline__ uint32_t smem_u32(const void* p) {
    uint32_t a;
    asm("{ .reg .u64 t; cvta.to.shared.u64 t, %1; cvt.u32.u64 %0, t; }" : "=r"(a) : "l"(p));
    return a;
}
__device__ __forceinline__ float tf32r(float x) {
    float r; asm("cvt.rna.tf32.f32 %0, %1;" : "=f"(r) : "f"(x)); return r;
}
__device__ __forceinline__ void cp_async16(uint32_t dst, const void* src) {
    asm volatile("cp.async.cg.shared.global [%0], [%1], 16;" :: "r"(dst), "l"(src) : "memory");
}
__device__ __forceinline__ void cp_commit() {
    asm volatile("cp.async.commit_group;" ::: "memory");
}
__device__ __forceinline__ void cp_wait0() {
    asm volatile("cp.async.wait_group 0;" ::: "memory");
}
// m16n8k8 tf32 mma: D = A*B + D
__device__ __forceinline__ void mma_tf32(float* c, const uint32_t* a, const uint32_t* b) {
    asm volatile(
        "mma.sync.aligned.m16n8k8.row.col.f32.tf32.tf32.f32 "
        "{%0,%1,%2,%3}, {%4,%5,%6,%7}, {%8,%9}, {%0,%1,%2,%3};"
        : "+f"(c[0]), "+f"(c[1]), "+f"(c[2]), "+f"(c[3])
        : "r"(a[0]), "r"(a[1]), "r"(a[2]), "r"(a[3]), "r"(b[0]), "r"(b[1]));
}

// ---------------- packed f32x2 helpers (attention) ----------------
__device__ __forceinline__ unsigned long long dup2(float v) {
    unsigned long long r;
    unsigned int u = __float_as_uint(v);
    asm("mov.b64 %0, {%1, %1};" : "=l"(r) : "r"(u));
    return r;
}
__device__ __forceinline__ void fma2(unsigned long long& c, unsigned long long a, unsigned long long b) {
    asm("fma.rn.f32x2 %0, %1, %2, %3;" : "=l"(c) : "l"(a), "l"(b), "l"(c));
}
__device__ __forceinline__ float2 un2(unsigned long long u) {
    float2 f;
    f.x = __uint_as_float((unsigned int)(u & 0xffffffffu));
    f.y = __uint_as_float((unsigned int)(u >> 32));
    return f;
}

// ================= prepass kernels =================
__global__ void cvt_round_k(const float* __restrict__ in, float* __restrict__ out, int n4) {
    int i = blockIdx.x * blockDim.x + threadIdx.x;
    int stride = gridDim.x * blockDim.x;
    for (; i < n4; i += stride) {
        float4 v = ((const float4*)in)[i];
        v.x = tf32r(v.x); v.y = tf32r(v.y); v.z = tf32r(v.z); v.w = tf32r(v.w);
        ((float4*)out)[i] = v;
    }
}

// W[K,N] -> Wt[N,K] with tf32 rounding. grid(N/32, K/32), block(32,8)
__global__ void transpose_cvt_k(const float* __restrict__ W, float* __restrict__ Wt, int K, int N) {
    __shared__ float t[32][33];
    int bx = blockIdx.x * 32, by = blockIdx.y * 32;
#pragma unroll
    for (int i = 0; i < 4; ++i)
        t[threadIdx.y + i * 8][threadIdx.x] = W[(size_t)(by + threadIdx.y + i * 8) * N + bx + threadIdx.x];
    __syncthreads();
#pragma unroll
    for (int i = 0; i < 4; ++i)
        Wt[(size_t)(bx + threadIdx.y + i * 8) * K + by + threadIdx.x] =
            tf32r(t[threadIdx.x][threadIdx.y + i * 8]);
}

// ================= tf32 mma.sync GEMM =================
// C[M,N] = A[M,K] @ Bt[N,K]^T + bias. Both operands K-major, tf32-rounded.
// CTA 128x128, BK=32, 256 threads (8 warps, warp tile 64x32).
#define TSTR 36                      // smem row stride (floats), conflict-free
#define TILE_F (128 * TSTR)          // 4608 floats per operand tile
#define GEMM_SMEM (2 * 2 * TILE_F * 4)  // 73728 bytes

__global__ __launch_bounds__(256, 2)
void gemm_mma(const float* __restrict__ A, const float* __restrict__ Bt,
              const float* __restrict__ bias, float* __restrict__ C,
              int M, int N, int K)
{
    extern __shared__ float sm[];
    const uint32_t sbase = smem_u32(sm);

    const int tid  = threadIdx.x;
    const int lane = tid & 31;
    const int wid  = tid >> 5;
    const int wm   = wid & 1;        // 2 warps in M
    const int wn   = wid >> 1;       // 4 warps in N
    const int g    = lane >> 2;      // group 0..7
    const int t    = lane & 3;       // 0..3
    const int m0 = blockIdx.y * 128, n0 = blockIdx.x * 128;

    const int lr = tid >> 3, lkq = tid & 7;   // loader: row pairs via +128? no: c=tid+256*i

    float c[4][4][4];
#pragma unroll
    for (int i = 0; i < 4; ++i)
#pragma unroll
        for (int j = 0; j < 4; ++j)
#pragma unroll
            for (int q = 0; q < 4; ++q) c[i][j][q] = 0.f;

#define LOAD_TILE(kt, buf)                                                        \
    do {                                                                          \
        uint32_t dA = sbase + (buf) * 2 * TILE_F * 4;                             \
        uint32_t dB = dA + TILE_F * 4;                                            \
        int k0 = (kt) * 32;                                                       \
        _Pragma("unroll")                                                         \
        for (int i = 0; i < 4; ++i) {                                             \
            int cc = tid + 256 * i;                                               \
            int r = cc >> 3, kq = cc & 7;                                         \
            cp_async16(dA + (r * TSTR + kq * 4) * 4,                              \
                       A + (size_t)(m0 + r) * K + k0 + kq * 4);                   \
            cp_async16(dB + (r * TSTR + kq * 4) * 4,                              \
                       Bt + (size_t)(n0 + r) * K + k0 + kq * 4);                  \
        }                                                                         \
        cp_commit();                                                              \
    } while (0)

    LOAD_TILE(0, 0);
    cp_wait0();
    __syncthreads();

    const int nk = K / 32;
    int cur = 0;
    for (int kt = 0; kt < nk; ++kt) {
        if (kt + 1 < nk) LOAD_TILE(kt + 1, cur ^ 1);

        const float* as = sm + cur * 2 * TILE_F + (wm * 64 + g) * TSTR;
        const float* bs = sm + cur * 2 * TILE_F + TILE_F + (wn * 32 + g) * TSTR;
#pragma unroll
        for (int ks = 0; ks < 4; ++ks) {
            const int kk = ks * 8 + t;
            uint32_t af[4][4], bf[4][2];
#pragma unroll
            for (int mt = 0; mt < 4; ++mt) {
                const float* p = as + mt * 16 * TSTR + kk;
                af[mt][0] = __float_as_uint(p[0]);
                af[mt][1] = __float_as_uint(p[8 * TSTR]);
                af[mt][2] = __float_as_uint(p[4]);
                af[mt][3] = __float_as_uint(p[8 * TSTR + 4]);
            }
#pragma unroll
            for (int nt = 0; nt < 4; ++nt) {
                const float* p = bs + nt * 8 * TSTR + kk;
                bf[nt][0] = __float_as_uint(p[0]);
                bf[nt][1] = __float_as_uint(p[4]);
            }
#pragma unroll
            for (int mt = 0; mt < 4; ++mt)
#pragma unroll
                for (int nt = 0; nt < 4; ++nt)
                    mma_tf32(c[mt][nt], af[mt], bf[nt]);
        }

        if (kt + 1 < nk) {
            cp_wait0();
            __syncthreads();
            cur ^= 1;
        }
    }
#undef LOAD_TILE

    // epilogue: c0,c1 -> (row=g, col=2t..2t+1) ; c2,c3 -> row g+8
#pragma unroll
    for (int mt = 0; mt < 4; ++mt) {
#pragma unroll
        for (int nt = 0; nt < 4; ++nt) {
            int row0 = m0 + wm * 64 + mt * 16 + g;
            int col  = n0 + wn * 32 + nt * 8 + t * 2;
            float b0 = bias[col], b1 = bias[col + 1];
            float2 v0 = make_float2(c[mt][nt][0] + b0, c[mt][nt][1] + b1);
            float2 v1 = make_float2(c[mt][nt][2] + b0, c[mt][nt][3] + b1);
            *(float2*)(C + (size_t)row0 * N + col)       = v0;
            *(float2*)(C + (size_t)(row0 + 8) * N + col) = v1;
        }
    }
}

// ---------------- Attention: per (b,h,64-query-tile) block ----------------
#define SST 68
__global__ __launch_bounds__(256)
void attn_kernel(const float* __restrict__ qkv, const int* __restrict__ adj,
                 float* __restrict__ y)
{
    extern __shared__ float smf[];
    float* S     = smf;                      // 512*68
    float* Qt    = smf + 512 * SST;          // 64*68 (transposed)
    float* KV    = Qt + 64 * SST;            // 64*68
    float* red   = KV + 64 * SST;            // 256
    float* rmaxs = red + 256;                // 64
    float* rsums = rmaxs + 64;               // 64

    const int t  = threadIdx.x;
    const int qt = blockIdx.x;
    const int bh = blockIdx.y;
    const int b  = bh >> 4, h = bh & 15;

    const size_t rowbase = (size_t)b * N_ * (3 * E_);
    const int qcol = h * DH_;
    const int kcol = E_ + h * DH_;
    const int vcol = 2 * E_ + h * DH_;

#pragma unroll
    for (int i = 0; i < 4; ++i) {
        int fid = t + i * 256;
        int row = fid >> 4, d4 = fid & 15;
        float4 v = *(const float4*)(qkv + rowbase + (size_t)(qt * 64 + row) * (3 * E_) + qcol + d4 * 4);
        Qt[(d4*4+0)*SST + row] = v.x;
        Qt[(d4*4+1)*SST + row] = v.y;
        Qt[(d4*4+2)*SST + row] = v.z;
        Qt[(d4*4+3)*SST + row] = v.w;
    }

    const int tc = t & 15, tr = t >> 4;
    const float scale = 0.125f;

    for (int kt = 0; kt < 8; ++kt) {
        __syncthreads();
#pragma unroll
        for (int i = 0; i < 4; ++i) {
            int fid = t + i * 256;
            int row = fid >> 4, d4 = fid & 15;
            float4 v = *(const float4*)(qkv + rowbase + (size_t)(kt * 64 + row) * (3 * E_) + kcol + d4 * 4);
            KV[(d4*4+0)*SST + row] = v.x;
            KV[(d4*4+1)*SST + row] = v.y;
            KV[(d4*4+2)*SST + row] = v.z;
            KV[(d4*4+3)*SST + row] = v.w;
        }
        __syncthreads();

        unsigned long long acc[4][2];
#pragma unroll
        for (int i = 0; i < 4; ++i) { acc[i][0] = 0ull; acc[i][1] = 0ull; }

#pragma unroll 16
        for (int d = 0; d < 64; ++d) {
            float4 kf = *(const float4*)(KV + d * SST + tc * 4);
            const unsigned long long* q2 = (const unsigned long long*)(Qt + d * SST + tr * 4);
            unsigned long long qa = q2[0], qb = q2[1];
            unsigned long long k0 = dup2(kf.x), k1 = dup2(kf.y), k2 = dup2(kf.z), k3 = dup2(kf.w);
            fma2(acc[0][0], k0, qa); fma2(acc[0][1], k0, qb);
            fma2(acc[1][0], k1, qa); fma2(acc[1][1], k1, qb);
            fma2(acc[2][0], k2, qa); fma2(acc[2][1], k2, qb);
            fma2(acc[3][0], k3, qa); fma2(acc[3][1], k3, qb);
        }

        int qg0 = qt * 64 + tr * 4;
#pragma unroll
        for (int ci = 0; ci < 4; ++ci) {
            int kg = kt * 64 + tc * 4 + ci;
            float2 p0 = un2(acc[ci][0]), p1 = un2(acc[ci][1]);
            float vals[4] = { p0.x, p0.y, p1.x, p1.y };
            float o4[4];
#pragma unroll
            for (int ri = 0; ri < 4; ++ri) {
                int qg = qg0 + ri;
                bool m = (adj[qg * N_ + kg] != 0) || (qg == kg);
                o4[ri] = m ? vals[ri] * scale : -1e30f;
            }
            *(float4*)(S + (size_t)kg * SST + tr * 4) =
                make_float4(o4[0], o4[1], o4[2], o4[3]);
        }
    }
    __syncthreads();

    {
        int r = t & 63, seg = t >> 6;
        float mx = -3.0e38f;
#pragma unroll 8
        for (int c = seg * 128; c < seg * 128 + 128; ++c)
            mx = fmaxf(mx, S[c * SST + r]);
        red[seg * 64 + r] = mx;
        __syncthreads();
        if (t < 64)
            rmaxs[t] = fmaxf(fmaxf(red[t], red[64 + t]), fmaxf(red[128 + t], red[192 + t]));
        __syncthreads();
        float rm = rmaxs[r];
        float sum = 0.f;
#pragma unroll 8
        for (int c = seg * 128; c < seg * 128 + 128; ++c) {
            float p = __expf(S[c * SST + r] - rm);
            S[c * SST + r] = p;
            sum += p;
        }
        red[seg * 64 + r] = sum;
        __syncthreads();
        if (t < 64)
            rsums[t] = red[t] + red[64 + t] + red[128 + t] + red[192 + t];
    }

    const int tv = tc;
    unsigned long long oacc[4][2];
#pragma unroll
    for (int i = 0; i < 4; ++i) { oacc[i][0] = 0ull; oacc[i][1] = 0ull; }

    for (int kt = 0; kt < 8; ++kt) {
        __syncthreads();
#pragma unroll
        for (int i = 0; i < 4; ++i) {
            int fid = t + i * 256;
            int row = fid >> 4, d4 = fid & 15;
            *(float4*)(KV + row * SST + d4 * 4) =
                *(const float4*)(qkv + rowbase + (size_t)(kt * 64 + row) * (3 * E_) + vcol + d4 * 4);
        }
        __syncthreads();

#pragma unroll 16
        for (int j = 0; j < 64; ++j) {
            float4 pf = *(const float4*)(S + (size_t)(kt * 64 + j) * SST + tr * 4);
            const unsigned long long* v2 = (const unsigned long long*)(KV + j * SST + tv * 4);
            unsigned long long va = v2[0], vb = v2[1];
            unsigned long long p0 = dup2(pf.x), p1 = dup2(pf.y), p2 = dup2(pf.z), p3 = dup2(pf.w);
            fma2(oacc[0][0], p0, va); fma2(oacc[0][1], p0, vb);
            fma2(oacc[1][0], p1, va); fma2(oacc[1][1], p1, vb);
            fma2(oacc[2][0], p2, va); fma2(oacc[2][1], p2, vb);
            fma2(oacc[3][0], p3, va); fma2(oacc[3][1], p3, vb);
        }
    }

#pragma unroll
    for (int ri = 0; ri < 4; ++ri) {
        int r = tr * 4 + ri;
        float inv = 1.0f / rsums[r];
        float2 p0 = un2(oacc[ri][0]), p1 = un2(oacc[ri][1]);
        // tf32-round: y feeds the tf32 output projection
        float4 o = make_float4(tf32r(p0.x * inv), tf32r(p0.y * inv),
                               tf32r(p1.x * inv), tf32r(p1.y * inv));
        *(float4*)(y + (size_t)(b * N_ + qt * 64 + r) * E_ + h * DH_ + tv * 4) = o;
    }
}

// ---------------- launch ----------------
extern "C" void kernel_launch(void* const* d_in, const int* in_sizes, int n_in,
                              void* d_out, int out_size) {
    const float* x     = (const float*)d_in[0];
    const float* Wqkv  = (const float*)d_in[1];
    const float* bqkv  = (const float*)d_in[2];
    const float* Wproj = (const float*)d_in[3];
    const float* bproj = (const float*)d_in[4];
    const int*   adj   = (const int*)d_in[5];

    float *qkv = nullptr, *yb = nullptr, *xr = nullptr, *wqkvT = nullptr, *wprojT = nullptr;
    cudaGetSymbolAddress((void**)&qkv,    g_qkv);
    cudaGetSymbolAddress((void**)&yb,     g_y);
    cudaGetSymbolAddress((void**)&xr,     g_xr);
    cudaGetSymbolAddress((void**)&wqkvT,  g_wqkvT);
    cudaGetSymbolAddress((void**)&wprojT, g_wprojT);

    const int ATT_SMEM = (512 * SST + 2 * 64 * SST + 256 + 128) * (int)sizeof(float);
    cudaFuncSetAttribute(attn_kernel, cudaFuncAttributeMaxDynamicSharedMemorySize, ATT_SMEM);
    cudaFuncSetAttribute(gemm_mma, cudaFuncAttributeMaxDynamicSharedMemorySize, GEMM_SMEM);

    // prepass: tf32-round x; transpose+round weights
    int n4 = (B_ * N_ * E_) / 4;
    cvt_round_k<<<2048, 256>>>(x, xr, n4);
    transpose_cvt_k<<<dim3(3 * E_ / 32, E_ / 32), dim3(32, 8)>>>(Wqkv, wqkvT, E_, 3 * E_);
    transpose_cvt_k<<<dim3(E_ / 32, E_ / 32), dim3(32, 8)>>>(Wproj, wprojT, E_, E_);

    // 1) QKV projection (tensor cores via mma.sync tf32)
    dim3 g1(3 * E_ / 128, (B_ * N_) / 128);
    gemm_mma<<<g1, 256, GEMM_SMEM>>>(xr, wqkvT, bqkv, qkv, B_ * N_, 3 * E_, E_);

    // 2) masked attention (fp32 SIMT)
    dim3 ga(N_ / 64, B_ * H_);
    attn_kernel<<<ga, 256, ATT_SMEM>>>(qkv, adj, yb);

    // 3) output projection (tensor cores via mma.sync tf32)
    dim3 g3(E_ / 128, (B_ * N_) / 128);
    gemm_mma<<<g3, 256, GEMM_SMEM>>>(yb, wprojT, bproj, (float*)d_out, B_ * N_, E_, E_);
}

// round 8
// speedup vs baseline: 1.8757x; 1.0201x over previous
#include <cuda_runtime.h>
#include <cstdint>

#define B_  64
#define N_  512
#define E_  1024
#define H_  16
#define DH_ 64

// Scratch (allocation-free rule: __device__ globals)
__device__ float    g_qkv[(size_t)B_ * N_ * 3 * E_];   // [B*N, 3E]
__device__ float    g_y[(size_t)B_ * N_ * E_];         // [B*N, E]
__device__ float    g_xr[(size_t)B_ * N_ * E_];        // tf32-rounded x
__device__ float    g_wqkvT[(size_t)3 * E_ * E_];      // [3E, E] = Wqkv^T
__device__ float    g_wprojT[(size_t)E_ * E_];         // [E, E]  = Wproj^T
__device__ uint32_t g_mask[N_ * 16];                   // (adj|I) bitmask, 16 words/row

// ================= helpers =================
__device__ __forceinline__ uint32_t smem_u32(const void* p) {
    uint32_t a;
    asm("{ .reg .u64 t; cvta.to.shared.u64 t, %1; cvt.u32.u64 %0, t; }" : "=r"(a) : "l"(p));
    return a;
}
__device__ __forceinline__ float tf32r(float x) {
    float r; asm("cvt.rna.tf32.f32 %0, %1;" : "=f"(r) : "f"(x)); return r;
}
__device__ __forceinline__ void cp_async16(uint32_t dst, const void* src) {
    asm volatile("cp.async.cg.shared.global [%0], [%1], 16;" :: "r"(dst), "l"(src) : "memory");
}
__device__ __forceinline__ void cp_commit() {
    asm volatile("cp.async.commit_group;" ::: "memory");
}
__device__ __forceinline__ void cp_wait0() {
    asm volatile("cp.async.wait_group 0;" ::: "memory");
}
// m16n8k8 tf32 mma: D = A*B + D
__device__ __forceinline__ void mma_tf32(float* c, const uint32_t* a, const uint32_t* b) {
    asm volatile(
        "mma.sync.aligned.m16n8k8.row.col.f32.tf32.tf32.f32 "
        "{%0,%1,%2,%3}, {%4,%5,%6,%7}, {%8,%9}, {%0,%1,%2,%3};"
        : "+f"(c[0]), "+f"(c[1]), "+f"(c[2]), "+f"(c[3])
        : "r"(a[0]), "r"(a[1]), "r"(a[2]), "r"(a[3]), "r"(b[0]), "r"(b[1]));
}
// fast exp: magic-round + degree-6 Taylor of 2^f on [-0.5, 0.5] (FMA pipe, no MUFU)
__device__ __forceinline__ float fexp(float x) {
    float tt = fmaxf(x * 1.4426950408889634f, -126.0f);
    float z  = tt + 12582912.0f;                 // round-to-nearest-int
    int   n  = __float_as_int(z) - 0x4B400000;   // integer part
    float f  = tt - (z - 12582912.0f);           // frac in [-0.5, 0.5]
    float p;
    p = fmaf(f, 1.5403530393e-4f, 1.3333558146e-3f);
    p = fmaf(f, p, 9.6181291076e-3f);
    p = fmaf(f, p, 5.5504108665e-2f);
    p = fmaf(f, p, 2.4022650696e-1f);
    p = fmaf(f, p, 6.9314718056e-1f);
    p = fmaf(f, p, 1.0f);
    return __int_as_float((n + 127) << 23) * p;
}

// ---------------- packed f32x2 helpers (attention) ----------------
__device__ __forceinline__ unsigned long long dup2(float v) {
    unsigned long long r;
    unsigned int u = __float_as_uint(v);
    asm("mov.b64 %0, {%1, %1};" : "=l"(r) : "r"(u));
    return r;
}
__device__ __forceinline__ void fma2(unsigned long long& c, unsigned long long a, unsigned long long b) {
    asm("fma.rn.f32x2 %0, %1, %2, %3;" : "=l"(c) : "l"(a), "l"(b), "l"(c));
}
__device__ __forceinline__ float2 un2(unsigned long long u) {
    float2 f;
    f.x = __uint_as_float((unsigned int)(u & 0xffffffffu));
    f.y = __uint_as_float((unsigned int)(u >> 32));
    return f;
}

// ================= prepass kernels =================
__global__ void cvt_round_k(const float* __restrict__ in, float* __restrict__ out, int n4) {
    int i = blockIdx.x * blockDim.x + threadIdx.x;
    int stride = gridDim.x * blockDim.x;
    for (; i < n4; i += stride) {
        float4 v = ((const float4*)in)[i];
        v.x = tf32r(v.x); v.y = tf32r(v.y); v.z = tf32r(v.z); v.w = tf32r(v.w);
        ((float4*)out)[i] = v;
    }
}

// W[K,N] -> Wt[N,K] with tf32 rounding. grid(N/32, K/32), block(32,8)
__global__ void transpose_cvt_k(const float* __restrict__ W, float* __restrict__ Wt, int K, int N) {
    __shared__ float t[32][33];
    int bx = blockIdx.x * 32, by = blockIdx.y * 32;
#pragma unroll
    for (int i = 0; i < 4; ++i)
        t[threadIdx.y + i * 8][threadIdx.x] = W[(size_t)(by + threadIdx.y + i * 8) * N + bx + threadIdx.x];
    __syncthreads();
#pragma unroll
    for (int i = 0; i < 4; ++i)
        Wt[(size_t)(bx + threadIdx.y + i * 8) * K + by + threadIdx.x] =
            tf32r(t[threadIdx.x][threadIdx.y + i * 8]);
}

// (adj | I) -> bitmask, one warp per row
__global__ void mask_ballot_k(const int* __restrict__ adj, uint32_t* __restrict__ mb) {
    int gw = (blockIdx.x * blockDim.x + threadIdx.x) >> 5;
    int lane = threadIdx.x & 31;
    if (gw >= N_) return;
    int r = gw;
#pragma unroll
    for (int w = 0; w < 16; ++w) {
        int c = w * 32 + lane;
        int v = (adj[(size_t)r * N_ + c] != 0) || (c == r);
        uint32_t word = __ballot_sync(0xffffffffu, v);
        if (lane == 0) mb[r * 16 + w] = word;
    }
}

// ================= tf32 mma.sync GEMM (proven in R4) =================
#define TSTR 36
#define TILE_F (128 * TSTR)
#define GEMM_SMEM (2 * 2 * TILE_F * 4)

__global__ __launch_bounds__(256, 2)
void gemm_mma(const float* __restrict__ A, const float* __restrict__ Bt,
              const float* __restrict__ bias, float* __restrict__ C,
              int M, int N, int K)
{
    extern __shared__ float sm[];
    const uint32_t sbase = smem_u32(sm);

    const int tid  = threadIdx.x;
    const int lane = tid & 31;
    const int wid  = tid >> 5;
    const int wm   = wid & 1;
    const int wn   = wid >> 1;
    const int g    = lane >> 2;
    const int t    = lane & 3;
    const int m0 = blockIdx.y * 128, n0 = blockIdx.x * 128;

    float c[4][4][4];
#pragma unroll
    for (int i = 0; i < 4; ++i)
#pragma unroll
        for (int j = 0; j < 4; ++j)
#pragma unroll
            for (int q = 0; q < 4; ++q) c[i][j][q] = 0.f;

#define LOAD_TILE(kt, buf)                                                        \
    do {                                                                          \
        uint32_t dA = sbase + (buf) * 2 * TILE_F * 4;                             \
        uint32_t dB = dA + TILE_F * 4;                                            \
        int k0 = (kt) * 32;                                                       \
        _Pragma("unroll")                                                         \
        for (int i = 0; i < 4; ++i) {                                             \
            int cc = tid + 256 * i;                                               \
            int r = cc >> 3, kq = cc & 7;                                         \
            cp_async16(dA + (r * TSTR + kq * 4) * 4,                              \
                       A + (size_t)(m0 + r) * K + k0 + kq * 4);                   \
            cp_async16(dB + (r * TSTR + kq * 4) * 4,                              \
                       Bt + (size_t)(n0 + r) * K + k0 + kq * 4);                  \
        }                                                                         \
        cp_commit();                                                              \
    } while (0)

    LOAD_TILE(0, 0);
    cp_wait0();
    __syncthreads();

    const int nk = K / 32;
    int cur = 0;
    for (int kt = 0; kt < nk; ++kt) {
        if (kt + 1 < nk) LOAD_TILE(kt + 1, cur ^ 1);

        const float* as = sm + cur * 2 * TILE_F + (wm * 64 + g) * TSTR;
        const float* bs = sm + cur * 2 * TILE_F + TILE_F + (wn * 32 + g) * TSTR;
#pragma unroll
        for (int ks = 0; ks < 4; ++ks) {
            const int kk = ks * 8 + t;
            uint32_t af[4][4], bf[4][2];
#pragma unroll
            for (int mt = 0; mt < 4; ++mt) {
                const float* p = as + mt * 16 * TSTR + kk;
                af[mt][0] = __float_as_uint(p[0]);
                af[mt][1] = __float_as_uint(p[8 * TSTR]);
                af[mt][2] = __float_as_uint(p[4]);
                af[mt][3] = __float_as_uint(p[8 * TSTR + 4]);
            }
#pragma unroll
            for (int nt = 0; nt < 4; ++nt) {
                const float* p = bs + nt * 8 * TSTR + kk;
                bf[nt][0] = __float_as_uint(p[0]);
                bf[nt][1] = __float_as_uint(p[4]);
            }
#pragma unroll
            for (int mt = 0; mt < 4; ++mt)
#pragma unroll
                for (int nt = 0; nt < 4; ++nt)
                    mma_tf32(c[mt][nt], af[mt], bf[nt]);
        }

        if (kt + 1 < nk) {
            cp_wait0();
            __syncthreads();
            cur ^= 1;
        }
    }
#undef LOAD_TILE

#pragma unroll
    for (int mt = 0; mt < 4; ++mt) {
#pragma unroll
        for (int nt = 0; nt < 4; ++nt) {
            int row0 = m0 + wm * 64 + mt * 16 + g;
            int col  = n0 + wn * 32 + nt * 8 + t * 2;
            float b0 = bias[col], b1 = bias[col + 1];
            float2 v0 = make_float2(c[mt][nt][0] + b0, c[mt][nt][1] + b1);
            float2 v1 = make_float2(c[mt][nt][2] + b0, c[mt][nt][3] + b1);
            *(float2*)(C + (size_t)row0 * N + col)       = v0;
            *(float2*)(C + (size_t)(row0 + 8) * N + col) = v1;
        }
    }
}

// ---------------- Attention: per (b,h,64-query-tile) block (R4-proven skeleton) ----------------
// Changes vs R4: adj -> smem bitmask bit-test; __expf -> fexp polynomial.
#define SST 68
// smem float offsets
#define A_S    0                               // S^T [512][68]
#define A_QT   (512 * SST)                     // Qt  [64][68]
#define A_KV   (A_QT + 64 * SST)               // KV  [64][68]
#define A_RED  (A_KV + 64 * SST)               // red [256]
#define A_RMX  (A_RED + 256)                   // rmaxs [64]
#define A_RSM  (A_RMX + 64)                    // rsums [64]
#define A_MSK  (A_RSM + 64)                    // mask words [64][17]
#define ATT_SMEM ((A_MSK + 64 * 17) * 4)

__global__ __launch_bounds__(256)
void attn_kernel(const float* __restrict__ qkv, const uint32_t* __restrict__ mb,
                 float* __restrict__ y)
{
    extern __shared__ float sm[];
    float*    S     = sm + A_S;
    float*    Qt    = sm + A_QT;
    float*    KV    = sm + A_KV;
    float*    red   = sm + A_RED;
    float*    rmaxs = sm + A_RMX;
    float*    rsums = sm + A_RSM;
    uint32_t* mskw  = (uint32_t*)(sm + A_MSK);

    const int t  = threadIdx.x;
    const int qt = blockIdx.x;
    const int bh = blockIdx.y;
    const int b  = bh >> 4, h = bh & 15;

    const size_t rowbase = (size_t)b * N_ * (3 * E_);
    const int qcol = h * DH_;
    const int kcol = E_ + h * DH_;
    const int vcol = 2 * E_ + h * DH_;

    // load Q tile transposed + mask rows for this q-tile
#pragma unroll
    for (int i = 0; i < 4; ++i) {
        int fid = t + i * 256;
        int row = fid >> 4, d4 = fid & 15;
        float4 v = *(const float4*)(qkv + rowbase + (size_t)(qt * 64 + row) * (3 * E_) + qcol + d4 * 4);
        Qt[(d4*4+0)*SST + row] = v.x;
        Qt[(d4*4+1)*SST + row] = v.y;
        Qt[(d4*4+2)*SST + row] = v.z;
        Qt[(d4*4+3)*SST + row] = v.w;
    }
#pragma unroll
    for (int i = 0; i < 4; ++i) {
        int idx = t + i * 256;                 // 1024 words
        int row = idx >> 4, wd = idx & 15;
        mskw[row * 17 + wd] = mb[(qt * 64 + row) * 16 + wd];
    }

    const int tc = t & 15, tr = t >> 4;
    const float scale = 0.125f;

    // ---- Phase 1: S^T[c][r] = mask(scale * Q K^T) ----
    for (int kt = 0; kt < 8; ++kt) {
        __syncthreads();
#pragma unroll
        for (int i = 0; i < 4; ++i) {
            int fid = t + i * 256;
            int row = fid >> 4, d4 = fid & 15;
            float4 v = *(const float4*)(qkv + rowbase + (size_t)(kt * 64 + row) * (3 * E_) + kcol + d4 * 4);
            KV[(d4*4+0)*SST + row] = v.x;
            KV[(d4*4+1)*SST + row] = v.y;
            KV[(d4*4+2)*SST + row] = v.z;
            KV[(d4*4+3)*SST + row] = v.w;
        }
        __syncthreads();

        unsigned long long acc[4][2];
#pragma unroll
        for (int i = 0; i < 4; ++i) { acc[i][0] = 0ull; acc[i][1] = 0ull; }

#pragma unroll 16
        for (int d = 0; d < 64; ++d) {
            float4 kf = *(const float4*)(KV + d * SST + tc * 4);
            const unsigned long long* q2 = (const unsigned long long*)(Qt + d * SST + tr * 4);
            unsigned long long qa = q2[0], qb = q2[1];
            unsigned long long k0 = dup2(kf.x), k1 = dup2(kf.y), k2 = dup2(kf.z), k3 = dup2(kf.w);
            fma2(acc[0][0], k0, qa); fma2(acc[0][1], k0, qb);
            fma2(acc[1][0], k1, qa); fma2(acc[1][1], k1, qb);
            fma2(acc[2][0], k2, qa); fma2(acc[2][1], k2, qb);
            fma2(acc[3][0], k3, qa); fma2(acc[3][1], k3, qb);
        }

        // mask via smem bit-words: kg = kt*64 + tc*4 + ci
        const int wi   = kt * 2 + (tc >> 3);   // word index (constant per thread per kt)
        const int bit0 = (tc & 7) * 4;         // base bit for ci=0
        uint32_t mrow[4];
#pragma unroll
        for (int ri = 0; ri < 4; ++ri) mrow[ri] = mskw[(tr * 4 + ri) * 17 + wi];

#pragma unroll
        for (int ci = 0; ci < 4; ++ci) {
            int kg = kt * 64 + tc * 4 + ci;
            float2 p0 = un2(acc[ci][0]), p1 = un2(acc[ci][1]);
            float vals[4] = { p0.x, p0.y, p1.x, p1.y };
            float o4[4];
#pragma unroll
            for (int ri = 0; ri < 4; ++ri) {
                bool m = (mrow[ri] >> (bit0 + ci)) & 1u;
                o4[ri] = m ? vals[ri] * scale : -1e30f;
            }
            *(float4*)(S + (size_t)kg * SST + tr * 4) =
                make_float4(o4[0], o4[1], o4[2], o4[3]);
        }
    }
    __syncthreads();

    // ---- Phase 2: softmax over each row r (512 entries), polynomial exp ----
    {
        int r = t & 63, seg = t >> 6;
        float mx = -3.0e38f;
#pragma unroll 8
        for (int c = seg * 128; c < seg * 128 + 128; ++c)
            mx = fmaxf(mx, S[c * SST + r]);
        red[seg * 64 + r] = mx;
        __syncthreads();
        if (t < 64)
            rmaxs[t] = fmaxf(fmaxf(red[t], red[64 + t]), fmaxf(red[128 + t], red[192 + t]));
        __syncthreads();
        float rm = rmaxs[r];
        float sum = 0.f;
#pragma unroll 8
        for (int c = seg * 128; c < seg * 128 + 128; ++c) {
            float p = fexp(S[c * SST + r] - rm);
            S[c * SST + r] = p;
            sum += p;
        }
        red[seg * 64 + r] = sum;
        __syncthreads();
        if (t < 64)
            rsums[t] = red[t] + red[64 + t] + red[128 + t] + red[192 + t];
    }

    // ---- Phase 3: O = P V ----
    const int tv = tc;
    unsigned long long oacc[4][2];
#pragma unroll
    for (int i = 0; i < 4; ++i) { oacc[i][0] = 0ull; oacc[i][1] = 0ull; }

    for (int kt = 0; kt < 8; ++kt) {
        __syncthreads();
#pragma unroll
        for (int i = 0; i < 4; ++i) {
            int fid = t + i * 256;
            int row = fid >> 4, d4 = fid & 15;
            *(float4*)(KV + row * SST + d4 * 4) =
                *(const float4*)(qkv + rowbase + (size_t)(kt * 64 + row) * (3 * E_) + vcol + d4 * 4);
        }
        __syncthreads();

#pragma unroll 16
        for (int j = 0; j < 64; ++j) {
            float4 pf = *(const float4*)(S + (size_t)(kt * 64 + j) * SST + tr * 4);
            const unsigned long long* v2 = (const unsigned long long*)(KV + j * SST + tv * 4);
            unsigned long long va = v2[0], vb = v2[1];
            unsigned long long p0 = dup2(pf.x), p1 = dup2(pf.y), p2 = dup2(pf.z), p3 = dup2(pf.w);
            fma2(oacc[0][0], p0, va); fma2(oacc[0][1], p0, vb);
            fma2(oacc[1][0], p1, va); fma2(oacc[1][1], p1, vb);
            fma2(oacc[2][0], p2, va); fma2(oacc[2][1], p2, vb);
            fma2(oacc[3][0], p3, va); fma2(oacc[3][1], p3, vb);
        }
    }

#pragma unroll
    for (int ri = 0; ri < 4; ++ri) {
        int r = tr * 4 + ri;
        float inv = 1.0f / rsums[r];
        float2 p0 = un2(oacc[ri][0]), p1 = un2(oacc[ri][1]);
        // tf32-round: y feeds the tf32 output projection
        float4 o = make_float4(tf32r(p0.x * inv), tf32r(p0.y * inv),
                               tf32r(p1.x * inv), tf32r(p1.y * inv));
        *(float4*)(y + (size_t)(b * N_ + qt * 64 + r) * E_ + h * DH_ + tv * 4) = o;
    }
}

// ---------------- launch ----------------
extern "C" void kernel_launch(void* const* d_in, const int* in_sizes, int n_in,
                              void* d_out, int out_size) {
    const float* x     = (const float*)d_in[0];
    const float* Wqkv  = (const float*)d_in[1];
    const float* bqkv  = (const float*)d_in[2];
    const float* Wproj = (const float*)d_in[3];
    const float* bproj = (const float*)d_in[4];
    const int*   adj   = (const int*)d_in[5];

    float *qkv = nullptr, *yb = nullptr, *xr = nullptr, *wqkvT = nullptr, *wprojT = nullptr;
    uint32_t* mb = nullptr;
    cudaGetSymbolAddress((void**)&qkv,    g_qkv);
    cudaGetSymbolAddress((void**)&yb,     g_y);
    cudaGetSymbolAddress((void**)&xr,     g_xr);
    cudaGetSymbolAddress((void**)&wqkvT,  g_wqkvT);
    cudaGetSymbolAddress((void**)&wprojT, g_wprojT);
    cudaGetSymbolAddress((void**)&mb,     g_mask);

    cudaFuncSetAttribute(attn_kernel, cudaFuncAttributeMaxDynamicSharedMemorySize, ATT_SMEM);
    cudaFuncSetAttribute(gemm_mma, cudaFuncAttributeMaxDynamicSharedMemorySize, GEMM_SMEM);

    // prepass
    int n4 = (B_ * N_ * E_) / 4;
    cvt_round_k<<<2048, 256>>>(x, xr, n4);
    transpose_cvt_k<<<dim3(3 * E_ / 32, E_ / 32), dim3(32, 8)>>>(Wqkv, wqkvT, E_, 3 * E_);
    transpose_cvt_k<<<dim3(E_ / 32, E_ / 32), dim3(32, 8)>>>(Wproj, wprojT, E_, E_);
    mask_ballot_k<<<64, 256>>>(adj, mb);

    // 1) QKV projection (tensor cores via mma.sync tf32)
    dim3 g1(3 * E_ / 128, (B_ * N_) / 128);
    gemm_mma<<<g1, 256, GEMM_SMEM>>>(xr, wqkvT, bqkv, qkv, B_ * N_, 3 * E_, E_);

    // 2) masked attention (fp32 SIMT, bitmask + poly exp)
    dim3 ga(N_ / 64, B_ * H_);
    attn_kernel<<<ga, 256, ATT_SMEM>>>(qkv, mb, yb);

    // 3) output projection (tensor cores via mma.sync tf32)
    dim3 g3(E_ / 128, (B_ * N_) / 128);
    gemm_mma<<<g3, 256, GEMM_SMEM>>>(yb, wprojT, bproj, (float*)d_out, B_ * N_, E_, E_);
}

// round 9
// speedup vs baseline: 2.7558x; 1.4692x over previous
#include <cuda_runtime.h>
#include <cstdint>

#define B_  64
#define N_  512
#define E_  1024
#define H_  16
#define DH_ 64

// Scratch (allocation-free rule: __device__ globals)
__device__ float    g_qkv[(size_t)B_ * N_ * 3 * E_];   // [B*N, 3E], tf32-rounded
__device__ float    g_y[(size_t)B_ * N_ * E_];         // [B*N, E]
__device__ float    g_xr[(size_t)B_ * N_ * E_];        // tf32-rounded x
__device__ float    g_wqkvT[(size_t)3 * E_ * E_];      // [3E, E] = Wqkv^T
__device__ float    g_wprojT[(size_t)E_ * E_];         // [E, E]  = Wproj^T
__device__ uint32_t g_mask[N_ * 16];                   // (adj|I) bitmask
__device__ float    g_S[(size_t)B_ * H_ * N_ * N_];    // score/prob scratch [bh][q][k]

// ================= helpers =================
__device__ __forceinline__ uint32_t smem_u32(const void* p) {
    uint32_t a;
    asm("{ .reg .u64 t; cvta.to.shared.u64 t, %1; cvt.u32.u64 %0, t; }" : "=r"(a) : "l"(p));
    return a;
}
__device__ __forceinline__ float tf32r(float x) {
    float r; asm("cvt.rna.tf32.f32 %0, %1;" : "=f"(r) : "f"(x)); return r;
}
__device__ __forceinline__ void cp_async16(uint32_t dst, const void* src) {
    asm volatile("cp.async.cg.shared.global [%0], [%1], 16;" :: "r"(dst), "l"(src) : "memory");
}
__device__ __forceinline__ void cp_commit() {
    asm volatile("cp.async.commit_group;" ::: "memory");
}
__device__ __forceinline__ void cp_wait0() {
    asm volatile("cp.async.wait_group 0;" ::: "memory");
}
// m16n8k8 tf32 mma: D = A*B + D
__device__ __forceinline__ void mma_tf32(float* c, const uint32_t* a, const uint32_t* b) {
    asm volatile(
        "mma.sync.aligned.m16n8k8.row.col.f32.tf32.tf32.f32 "
        "{%0,%1,%2,%3}, {%4,%5,%6,%7}, {%8,%9}, {%0,%1,%2,%3};"
        : "+f"(c[0]), "+f"(c[1]), "+f"(c[2]), "+f"(c[3])
        : "r"(a[0]), "r"(a[1]), "r"(a[2]), "r"(a[3]), "r"(b[0]), "r"(b[1]));
}
// fast exp: magic-round + degree-6 Taylor of 2^f on [-0.5, 0.5] (FMA pipe, no MUFU)
__device__ __forceinline__ float fexp(float x) {
    float tt = fmaxf(x * 1.4426950408889634f, -126.0f);
    float z  = tt + 12582912.0f;
    int   n  = __float_as_int(z) - 0x4B400000;
    float f  = tt - (z - 12582912.0f);
    float p;
    p = fmaf(f, 1.5403530393e-4f, 1.3333558146e-3f);
    p = fmaf(f, p, 9.6181291076e-3f);
    p = fmaf(f, p, 5.5504108665e-2f);
    p = fmaf(f, p, 2.4022650696e-1f);
    p = fmaf(f, p, 6.9314718056e-1f);
    p = fmaf(f, p, 1.0f);
    return __int_as_float((n + 127) << 23) * p;
}

// ================= prepass kernels =================
__global__ void cvt_round_k(const float* __restrict__ in, float* __restrict__ out, int n4) {
    int i = blockIdx.x * blockDim.x + threadIdx.x;
    int stride = gridDim.x * blockDim.x;
    for (; i < n4; i += stride) {
        float4 v = ((const float4*)in)[i];
        v.x = tf32r(v.x); v.y = tf32r(v.y); v.z = tf32r(v.z); v.w = tf32r(v.w);
        ((float4*)out)[i] = v;
    }
}

__global__ void transpose_cvt_k(const float* __restrict__ W, float* __restrict__ Wt, int K, int N) {
    __shared__ float t[32][33];
    int bx = blockIdx.x * 32, by = blockIdx.y * 32;
#pragma unroll
    for (int i = 0; i < 4; ++i)
        t[threadIdx.y + i * 8][threadIdx.x] = W[(size_t)(by + threadIdx.y + i * 8) * N + bx + threadIdx.x];
    __syncthreads();
#pragma unroll
    for (int i = 0; i < 4; ++i)
        Wt[(size_t)(bx + threadIdx.y + i * 8) * K + by + threadIdx.x] =
            tf32r(t[threadIdx.x][threadIdx.y + i * 8]);
}

__global__ void mask_ballot_k(const int* __restrict__ adj, uint32_t* __restrict__ mb) {
    int gw = (blockIdx.x * blockDim.x + threadIdx.x) >> 5;
    int lane = threadIdx.x & 31;
    if (gw >= N_) return;
    int r = gw;
#pragma unroll
    for (int w = 0; w < 16; ++w) {
        int c = w * 32 + lane;
        int v = (adj[(size_t)r * N_ + c] != 0) || (c == r);
        uint32_t word = __ballot_sync(0xffffffffu, v);
        if (lane == 0) mb[r * 16 + w] = word;
    }
}

// ================= tf32 mma.sync GEMM (proven) =================
#define TSTR 36
#define TILE_F (128 * TSTR)
#define GEMM_SMEM (2 * 2 * TILE_F * 4)

__global__ __launch_bounds__(256, 2)
void gemm_mma(const float* __restrict__ A, const float* __restrict__ Bt,
              const float* __restrict__ bias, float* __restrict__ C,
              int M, int N, int K, int roundOut)
{
    extern __shared__ float sm[];
    const uint32_t sbase = smem_u32(sm);

    const int tid  = threadIdx.x;
    const int lane = tid & 31;
    const int wid  = tid >> 5;
    const int wm   = wid & 1;
    const int wn   = wid >> 1;
    const int g    = lane >> 2;
    const int t    = lane & 3;
    const int m0 = blockIdx.y * 128, n0 = blockIdx.x * 128;

    float c[4][4][4];
#pragma unroll
    for (int i = 0; i < 4; ++i)
#pragma unroll
        for (int j = 0; j < 4; ++j)
#pragma unroll
            for (int q = 0; q < 4; ++q) c[i][j][q] = 0.f;

#define LOAD_TILE(kt, buf)                                                        \
    do {                                                                          \
        uint32_t dA = sbase + (buf) * 2 * TILE_F * 4;                             \
        uint32_t dB = dA + TILE_F * 4;                                            \
        int k0 = (kt) * 32;                                                       \
        _Pragma("unroll")                                                         \
        for (int i = 0; i < 4; ++i) {                                             \
            int cc = tid + 256 * i;                                               \
            int r = cc >> 3, kq = cc & 7;                                         \
            cp_async16(dA + (r * TSTR + kq * 4) * 4,                              \
                       A + (size_t)(m0 + r) * K + k0 + kq * 4);                   \
            cp_async16(dB + (r * TSTR + kq * 4) * 4,                              \
                       Bt + (size_t)(n0 + r) * K + k0 + kq * 4);                  \
        }                                                                         \
        cp_commit();                                                              \
    } while (0)

    LOAD_TILE(0, 0);
    cp_wait0();
    __syncthreads();

    const int nk = K / 32;
    int cur = 0;
    for (int kt = 0; kt < nk; ++kt) {
        if (kt + 1 < nk) LOAD_TILE(kt + 1, cur ^ 1);

        const float* as = sm + cur * 2 * TILE_F + (wm * 64 + g) * TSTR;
        const float* bs = sm + cur * 2 * TILE_F + TILE_F + (wn * 32 + g) * TSTR;
#pragma unroll
        for (int ks = 0; ks < 4; ++ks) {
            const int kk = ks * 8 + t;
            uint32_t af[4][4], bf[4][2];
#pragma unroll
            for (int mt = 0; mt < 4; ++mt) {
                const float* p = as + mt * 16 * TSTR + kk;
                af[mt][0] = __float_as_uint(p[0]);
                af[mt][1] = __float_as_uint(p[8 * TSTR]);
                af[mt][2] = __float_as_uint(p[4]);
                af[mt][3] = __float_as_uint(p[8 * TSTR + 4]);
            }
#pragma unroll
            for (int nt = 0; nt < 4; ++nt) {
                const float* p = bs + nt * 8 * TSTR + kk;
                bf[nt][0] = __float_as_uint(p[0]);
                bf[nt][1] = __float_as_uint(p[4]);
            }
#pragma unroll
            for (int mt = 0; mt < 4; ++mt)
#pragma unroll
                for (int nt = 0; nt < 4; ++nt)
                    mma_tf32(c[mt][nt], af[mt], bf[nt]);
        }

        if (kt + 1 < nk) {
            cp_wait0();
            __syncthreads();
            cur ^= 1;
        }
    }
#undef LOAD_TILE

#pragma unroll
    for (int mt = 0; mt < 4; ++mt) {
#pragma unroll
        for (int nt = 0; nt < 4; ++nt) {
            int row0 = m0 + wm * 64 + mt * 16 + g;
            int col  = n0 + wn * 32 + nt * 8 + t * 2;
            float b0 = bias[col], b1 = bias[col + 1];
            float4 v = make_float4(c[mt][nt][0] + b0, c[mt][nt][1] + b1,
                                   c[mt][nt][2] + b0, c[mt][nt][3] + b1);
            if (roundOut) {
                v.x = tf32r(v.x); v.y = tf32r(v.y); v.z = tf32r(v.z); v.w = tf32r(v.w);
            }
            *(float2*)(C + (size_t)row0 * N + col)       = make_float2(v.x, v.y);
            *(float2*)(C + (size_t)(row0 + 8) * N + col) = make_float2(v.z, v.w);
        }
    }
}

// ================= attention stage 1: S = mask(scale * Q K^T) =================
#define QK_SMEM ((64 * 68 + 128 * 68 + 64 * 17) * 4)

__global__ __launch_bounds__(256)
void attn_qk(const float* __restrict__ qkv, const uint32_t* __restrict__ mb,
             float* __restrict__ Sg)
{
    extern __shared__ float sm[];
    float*    Qs   = sm;                       // [64][68]
    float*    Ks   = sm + 64 * 68;             // [128][68]
    uint32_t* mskw = (uint32_t*)(sm + 64 * 68 + 128 * 68);  // [64][17]
    const uint32_t sb = smem_u32(sm);

    const int t    = threadIdx.x;
    const int lane = t & 31;
    const int w    = t >> 5;
    const int g    = lane >> 2;
    const int tq   = lane & 3;
    const int wm   = w & 1;
    const int wn   = w >> 1;
    const int n0 = blockIdx.x * 128;
    const int qt = blockIdx.y;
    const int bh = blockIdx.z;
    const int b  = bh >> 4, h = bh & 15;

    const size_t rowbase = (size_t)b * N_ * (3 * E_);
    const int qcol = h * DH_;
    const int kcol = E_ + h * DH_;

#pragma unroll
    for (int i = 0; i < 4; ++i) {
        int fid = t + 256 * i;
        int row = fid >> 4, c4 = fid & 15;
        cp_async16(sb + (row * 68 + c4 * 4) * 4,
                   qkv + rowbase + (size_t)(qt * 64 + row) * (3 * E_) + qcol + c4 * 4);
    }
#pragma unroll
    for (int i = 0; i < 8; ++i) {
        int fid = t + 256 * i;
        int row = fid >> 4, c4 = fid & 15;
        cp_async16(sb + (64 * 68 + row * 68 + c4 * 4) * 4,
                   qkv + rowbase + (size_t)(n0 + row) * (3 * E_) + kcol + c4 * 4);
    }
    cp_commit();
#pragma unroll
    for (int i = 0; i < 4; ++i) {
        int idx = t + 256 * i;
        int row = idx >> 4, wd = idx & 15;
        mskw[row * 17 + wd] = mb[(qt * 64 + row) * 16 + wd];
    }
    cp_wait0();
    __syncthreads();

    float c[2][4][4];
#pragma unroll
    for (int i = 0; i < 2; ++i)
#pragma unroll
        for (int j = 0; j < 4; ++j)
#pragma unroll
            for (int q = 0; q < 4; ++q) c[i][j][q] = 0.f;

    const float* as = Qs + (wm * 32 + g) * 68;
    const float* bs = Ks + (wn * 32 + g) * 68;
#pragma unroll
    for (int ks = 0; ks < 8; ++ks) {
        const int kk = ks * 8 + tq;
        uint32_t af[2][4], bf[4][2];
#pragma unroll
        for (int mt = 0; mt < 2; ++mt) {
            const float* p = as + mt * 16 * 68 + kk;
            af[mt][0] = __float_as_uint(p[0]);
            af[mt][1] = __float_as_uint(p[8 * 68]);
            af[mt][2] = __float_as_uint(p[4]);
            af[mt][3] = __float_as_uint(p[8 * 68 + 4]);
        }
#pragma unroll
        for (int nt = 0; nt < 4; ++nt) {
            const float* p = bs + nt * 8 * 68 + kk;
            bf[nt][0] = __float_as_uint(p[0]);
            bf[nt][1] = __float_as_uint(p[4]);
        }
#pragma unroll
        for (int mt = 0; mt < 2; ++mt)
#pragma unroll
            for (int nt = 0; nt < 4; ++nt)
                mma_tf32(c[mt][nt], af[mt], bf[nt]);
    }

    const int wi = (n0 >> 5) + wn;
#pragma unroll
    for (int mt = 0; mt < 2; ++mt) {
        int r0 = wm * 32 + mt * 16 + g;
        uint32_t mw0 = mskw[r0 * 17 + wi];
        uint32_t mw1 = mskw[(r0 + 8) * 17 + wi];
#pragma unroll
        for (int nt = 0; nt < 4; ++nt) {
            int bit = nt * 8 + 2 * tq;
            int col = n0 + wn * 32 + bit;
            float2 v0, v1;
            v0.x = ((mw0 >> bit) & 1u)       ? c[mt][nt][0] * 0.125f : -1e30f;
            v0.y = ((mw0 >> (bit + 1)) & 1u) ? c[mt][nt][1] * 0.125f : -1e30f;
            v1.x = ((mw1 >> bit) & 1u)       ? c[mt][nt][2] * 0.125f : -1e30f;
            v1.y = ((mw1 >> (bit + 1)) & 1u) ? c[mt][nt][3] * 0.125f : -1e30f;
            size_t qrow = (size_t)bh * 512 + qt * 64 + r0;
            *(float2*)(Sg + qrow * 512 + col)       = v0;
            *(float2*)(Sg + (qrow + 8) * 512 + col) = v1;
        }
    }
}

// ================= attention stage 2: rowwise softmax (in place) =================
__global__ __launch_bounds__(256)
void attn_softmax(float* __restrict__ Sg)
{
    size_t row = (size_t)blockIdx.x * 8 + (threadIdx.x >> 5);
    int lane = threadIdx.x & 31;
    float* base = Sg + row * 512 + lane * 4;

    float4 v[4];
#pragma unroll
    for (int j = 0; j < 4; ++j) v[j] = *(float4*)(base + j * 128);

    float m = -3.0e38f;
#pragma unroll
    for (int j = 0; j < 4; ++j)
        m = fmaxf(fmaxf(fmaxf(m, v[j].x), fmaxf(v[j].y, v[j].z)), v[j].w);
#pragma unroll
    for (int o = 16; o > 0; o >>= 1)
        m = fmaxf(m, __shfl_xor_sync(0xffffffffu, m, o));

    float sum = 0.f;
#pragma unroll
    for (int j = 0; j < 4; ++j) {
        v[j].x = fexp(v[j].x - m); v[j].y = fexp(v[j].y - m);
        v[j].z = fexp(v[j].z - m); v[j].w = fexp(v[j].w - m);
        sum += (v[j].x + v[j].y) + (v[j].z + v[j].w);
    }
#pragma unroll
    for (int o = 16; o > 0; o >>= 1)
        sum += __shfl_xor_sync(0xffffffffu, sum, o);
    float inv = 1.0f / sum;

#pragma unroll
    for (int j = 0; j < 4; ++j) {
        v[j].x = tf32r(v[j].x * inv); v[j].y = tf32r(v[j].y * inv);
        v[j].z = tf32r(v[j].z * inv); v[j].w = tf32r(v[j].w * inv);
        *(float4*)(base + j * 128) = v[j];
    }
}

// ================= attention stage 3: O = P V =================
#define PV_SMEM (2 * 64 * 68 * 4)

__global__ __launch_bounds__(256)
void attn_pv(const float* __restrict__ qkv, const float* __restrict__ Sg,
             float* __restrict__ y)
{
    extern __shared__ float sm[];
    float* Ps = sm;                 // [64][68]
    float* Vt = sm + 64 * 68;       // [64][68]
    const uint32_t sb = smem_u32(sm);

    const int t    = threadIdx.x;
    const int lane = t & 31;
    const int w    = t >> 5;
    const int g    = lane >> 2;
    const int tq   = lane & 3;
    const int wm   = w & 3;
    const int wn   = w >> 2;
    const int qt = blockIdx.x;
    const int bh = blockIdx.y;
    const int b  = bh >> 4, h = bh & 15;

    const size_t rowbase = (size_t)b * N_ * (3 * E_);
    const int vcol = 2 * E_ + h * DH_;
    const size_t prow0 = (size_t)bh * 512 + qt * 64;

    float c[4][4];
#pragma unroll
    for (int j = 0; j < 4; ++j)
#pragma unroll
        for (int q = 0; q < 4; ++q) c[j][q] = 0.f;

    for (int kt = 0; kt < 8; ++kt) {
        if (kt) __syncthreads();
#pragma unroll
        for (int i = 0; i < 4; ++i) {
            int fid = t + 256 * i;
            int row = fid >> 4, c4 = fid & 15;
            cp_async16(sb + (row * 68 + c4 * 4) * 4,
                       Sg + (prow0 + row) * 512 + kt * 64 + c4 * 4);
        }
        cp_commit();
#pragma unroll
        for (int i = 0; i < 4; ++i) {
            int fid = t + 256 * i;
            int row = fid >> 4, c4 = fid & 15;
            float4 v = *(const float4*)(qkv + rowbase + (size_t)(kt * 64 + row) * (3 * E_) + vcol + c4 * 4);
            Vt[(c4 * 4 + 0) * 68 + row] = v.x;
            Vt[(c4 * 4 + 1) * 68 + row] = v.y;
            Vt[(c4 * 4 + 2) * 68 + row] = v.z;
            Vt[(c4 * 4 + 3) * 68 + row] = v.w;
        }
        cp_wait0();
        __syncthreads();

        const float* as = Ps + (wm * 16 + g) * 68;
        const float* bs = Vt + (wn * 32 + g) * 68;
#pragma unroll
        for (int ks = 0; ks < 8; ++ks) {
            const int kk = ks * 8 + tq;
            uint32_t af[4], bf[4][2];
            {
                const float* p = as + kk;
                af[0] = __float_as_uint(p[0]);
                af[1] = __float_as_uint(p[8 * 68]);
                af[2] = __float_as_uint(p[4]);
                af[3] = __float_as_uint(p[8 * 68 + 4]);
            }
#pragma unroll
            for (int nt = 0; nt < 4; ++nt) {
                const float* p = bs + nt * 8 * 68 + kk;
                bf[nt][0] = __float_as_uint(p[0]);
                bf[nt][1] = __float_as_uint(p[4]);
            }
#pragma unroll
            for (int nt = 0; nt < 4; ++nt)
                mma_tf32(c[nt], af, bf[nt]);
        }
    }

    int r0 = wm * 16 + g;
    size_t yrow = (size_t)(b * N_ + qt * 64 + r0);
#pragma unroll
    for (int nt = 0; nt < 4; ++nt) {
        int col = h * DH_ + wn * 32 + nt * 8 + 2 * tq;
        *(float2*)(y + yrow * E_ + col) =
            make_float2(tf32r(c[nt][0]), tf32r(c[nt][1]));
        *(float2*)(y + (yrow + 8) * E_ + col) =
            make_float2(tf32r(c[nt][2]), tf32r(c[nt][3]));
    }
}

// ---------------- launch ----------------
extern "C" void kernel_launch(void* const* d_in, const int* in_sizes, int n_in,
                              void* d_out, int out_size) {
    const float* x     = (const float*)d_in[0];
    const float* Wqkv  = (const float*)d_in[1];
    const float* bqkv  = (const float*)d_in[2];
    const float* Wproj = (const float*)d_in[3];
    const float* bproj = (const float*)d_in[4];
    const int*   adj   = (const int*)d_in[5];

    float *qkv = nullptr, *yb = nullptr, *xr = nullptr, *wqkvT = nullptr, *wprojT = nullptr, *Sg = nullptr;
    uint32_t* mb = nullptr;
    cudaGetSymbolAddress((void**)&qkv,    g_qkv);
    cudaGetSymbolAddress((void**)&yb,     g_y);
    cudaGetSymbolAddress((void**)&xr,     g_xr);
    cudaGetSymbolAddress((void**)&wqkvT,  g_wqkvT);
    cudaGetSymbolAddress((void**)&wprojT, g_wprojT);
    cudaGetSymbolAddress((void**)&mb,     g_mask);
    cudaGetSymbolAddress((void**)&Sg,     g_S);

    cudaFuncSetAttribute(gemm_mma, cudaFuncAttributeMaxDynamicSharedMemorySize, GEMM_SMEM);
    cudaFuncSetAttribute(attn_qk,  cudaFuncAttributeMaxDynamicSharedMemorySize, QK_SMEM);
    cudaFuncSetAttribute(attn_pv,  cudaFuncAttributeMaxDynamicSharedMemorySize, PV_SMEM);

    // prepass
    int n4 = (B_ * N_ * E_) / 4;
    cvt_round_k<<<2048, 256>>>(x, xr, n4);
    transpose_cvt_k<<<dim3(3 * E_ / 32, E_ / 32), dim3(32, 8)>>>(Wqkv, wqkvT, E_, 3 * E_);
    transpose_cvt_k<<<dim3(E_ / 32, E_ / 32), dim3(32, 8)>>>(Wproj, wprojT, E_, E_);
    mask_ballot_k<<<64, 256>>>(adj, mb);

    // 1) QKV projection (rounded output feeds attention mmas)
    dim3 g1(3 * E_ / 128, (B_ * N_) / 128);
    gemm_mma<<<g1, 256, GEMM_SMEM>>>(xr, wqkvT, bqkv, qkv, B_ * N_, 3 * E_, E_, 1);

    // 2) attention: QK^T -> softmax -> PV (all tensor-core / memory-bound passes)
    attn_qk<<<dim3(4, 8, 1024), 256, QK_SMEM>>>(qkv, mb, Sg);
    attn_softmax<<<(B_ * H_ * N_) / 8, 256>>>(Sg);
    attn_pv<<<dim3(8, 1024), 256, PV_SMEM>>>(qkv, Sg, yb);

    // 3) output projection
    dim3 g3(E_ / 128, (B_ * N_) / 128);
    gemm_mma<<<g3, 256, GEMM_SMEM>>>(yb, wprojT, bproj, (float*)d_out, B_ * N_, E_, E_, 0);
}